// round 3
// baseline (speedup 1.0000x reference)
#include <cuda_runtime.h>
#include <cstdint>

#define NN 131072
#define NE 4194304
#define FI 64

// ---------------- scratch (device globals: no allocation allowed) ----------
__device__ float g_deg [NN];         // degree, then dinv in-place
__device__ int   g_cnt [NN];         // in-degree histogram (by dst)
__device__ int   g_off [NN + 1];     // CSR row offsets (by dst)
__device__ int   g_cur [NN];         // scatter cursors
__device__ int   g_csrc[NE];         // CSR: src node per edge slot
__device__ float g_cw  [NE];         // CSR: normalized weight per edge slot
__device__ float g_T1[NN * FI];      // Tx1 = spmm(x)
__device__ float g_T2[NN * FI];      // Tx2 = 2*spmm(Tx1) - x
__device__ float g_T3[NN * FI];      // Tx3 = 2*spmm(Tx2) - Tx1
__device__ float g_B [256 * 256];    // packed weights [k-row][gate0|gate2 col]
__device__ float g_bias[256];        // b_x[g]+b_h[g] for gate0|gate2
__device__ int   g_any;              // detector: any odd word nonzero?
__device__ int   g_is64;             // 1 if edge_index is int64

// ---------------- edge-index access (dtype-robust, trap-proof) -------------
__device__ __forceinline__ int eidx(const void* ei, unsigned i) {
    int v;
    if (g_is64) v = (int)((const long long*)ei)[i];
    else        v = ((const int*)ei)[i];
    return v & (NN - 1);             // NN = 2^17: no-op for valid ids, trap-proof
}

// ---------------- f32x2 helpers (Blackwell packed fp32) --------------------
__device__ __forceinline__ unsigned long long pk2(float lo, float hi) {
    unsigned long long r;
    asm("mov.b64 %0, {%1, %2};" : "=l"(r)
        : "r"(__float_as_uint(lo)), "r"(__float_as_uint(hi)));
    return r;
}
__device__ __forceinline__ void upk2(unsigned long long v, float& lo, float& hi) {
    unsigned a, b;
    asm("mov.b64 {%0, %1}, %2;" : "=r"(a), "=r"(b) : "l"(v));
    lo = __uint_as_float(a); hi = __uint_as_float(b);
}
__device__ __forceinline__ void fma2(unsigned long long& d,
                                     unsigned long long a, unsigned long long b) {
    asm("fma.rn.f32x2 %0, %1, %2, %0;" : "+l"(d) : "l"(a), "l"(b));
}

// ---------------- prep kernels ---------------------------------------------
__global__ void k_zero() {
    int i = blockIdx.x * 256 + threadIdx.x;
    if (i < NN) { g_deg[i] = 0.f; g_cnt[i] = 0; }
    if (i == 0) { g_any = 0; }
}

// sample odd 32-bit words of the first 2*NE words: all-zero <=> int64 layout
__global__ void k_detect(const int* __restrict__ w) {
    int t = blockIdx.x * 256 + threadIdx.x;      // 4096 samples
    int stride = (2 * (NE / 4096));              // spread across first 2*NE words
    int v = w[(unsigned)(t * stride + 1)];
    if (__syncthreads_or(v != 0) && threadIdx.x == 0) atomicOr(&g_any, 1);
}
__global__ void k_setflag() { g_is64 = (g_any == 0); }

// degree (by src, weighted) + in-degree histogram (by dst)
__global__ void k_deg(const void* __restrict__ ei, const float* __restrict__ ew) {
    unsigned e = blockIdx.x * 256 + threadIdx.x;
    if (e >= NE) return;
    atomicAdd(&g_deg[eidx(ei, e)], ew[e]);
    atomicAdd(&g_cnt[eidx(ei, NE + e)], 1);
}

__global__ void k_dinv() {
    int i = blockIdx.x * 256 + threadIdx.x;
    if (i < NN) {
        float d = g_deg[i];
        g_deg[i] = (d > 0.f) ? rsqrtf(d) : 0.f;
    }
}

// single-block exclusive scan of g_cnt -> g_off, g_cur  (1024 threads)
__global__ void k_scan() {
    __shared__ int wsum[32];
    __shared__ int carry_s;
    const int tid  = threadIdx.x;
    const int lane = tid & 31;
    const int w    = tid >> 5;
    int carry = 0;
    for (int base = 0; base < NN; base += 1024) {
        int v = g_cnt[base + tid];
        int x = v;
#pragma unroll
        for (int d = 1; d < 32; d <<= 1) {
            int y = __shfl_up_sync(0xffffffffu, x, d);
            if (lane >= d) x += y;
        }
        if (lane == 31) wsum[w] = x;
        __syncthreads();
        if (w == 0) {
            int s = wsum[lane];
#pragma unroll
            for (int d = 1; d < 32; d <<= 1) {
                int y = __shfl_up_sync(0xffffffffu, s, d);
                if (lane >= d) s += y;
            }
            wsum[lane] = s;
        }
        __syncthreads();
        int incl = x + (w > 0 ? wsum[w - 1] : 0) + carry;
        int excl = incl - v;
        g_off[base + tid] = excl;
        g_cur[base + tid] = excl;
        if (tid == 1023) carry_s = incl;
        __syncthreads();
        carry = carry_s;
        __syncthreads();
    }
    if (tid == 0) g_off[NN] = carry;
}

// scatter edges into CSR slots (one int atomic per edge)
__global__ void k_scatter(const void* __restrict__ ei, const float* __restrict__ ew) {
    unsigned e = blockIdx.x * 256 + threadIdx.x;
    if (e >= NE) return;
    int s = eidx(ei, e);
    int d = eidx(ei, NE + e);
    float w = -g_deg[s] * ew[e] * g_deg[d];
    int pos = atomicAdd(&g_cur[d], 1);
    if (pos < NE) { g_csrc[pos] = s; g_cw[pos] = w; }
}

// Pack B[256x256]: row r = 64*kb + f -> W_x[g][kb][f][:] (g=0 cols<128, g=2 else)
__global__ void k_pack(const float* __restrict__ Wx, const float* __restrict__ bx,
                       const float* __restrict__ bh) {
    int i = blockIdx.x * 256 + threadIdx.x;   // 65536 total
    int r = i >> 8, j = i & 255;
    int kb = r >> 6, f = r & 63;
    int g  = (j < 128) ? 0 : 2;
    int jj = j & 127;
    g_B[i] = Wx[(((size_t)(g * 4 + kb) * 64 + f) * 128) + jj];
    if (r == 0) g_bias[j] = bx[g * 128 + jj] + bh[g * 128 + jj];
}

// ---------------- SpMM gather: out[d] = CHEB ? (2*sum - prev[d]) : sum ------
// One warp per dst node. 2 edges in flight (half-warps), float4 lanes.
template <bool CHEB>
__global__ void __launch_bounds__(256)
k_spmm(const float4* __restrict__ vin, const float4* __restrict__ prev,
       float4* __restrict__ vout) {
    const int node = blockIdx.x * 8 + (threadIdx.x >> 5);
    const int lane = threadIdx.x & 31;
    const int lh   = lane & 15;         // float4 slot within row
    const int half = lane >> 4;         // which of 2 parallel edges
    const int beg = g_off[node];
    const int end = g_off[node + 1];

    float4 acc = make_float4(0.f, 0.f, 0.f, 0.f);
    int i = beg + half;
    for (; i + 2 < end; i += 4) {
        int   s0 = g_csrc[i];
        int   s1 = g_csrc[i + 2];
        float w0 = g_cw[i];
        float w1 = g_cw[i + 2];
        float4 v0 = vin[(long)s0 * 16 + lh];
        float4 v1 = vin[(long)s1 * 16 + lh];
        acc.x = fmaf(w0, v0.x, acc.x); acc.y = fmaf(w0, v0.y, acc.y);
        acc.z = fmaf(w0, v0.z, acc.z); acc.w = fmaf(w0, v0.w, acc.w);
        acc.x = fmaf(w1, v1.x, acc.x); acc.y = fmaf(w1, v1.y, acc.y);
        acc.z = fmaf(w1, v1.z, acc.z); acc.w = fmaf(w1, v1.w, acc.w);
    }
    if (i < end) {
        int   s0 = g_csrc[i];
        float w0 = g_cw[i];
        float4 v0 = vin[(long)s0 * 16 + lh];
        acc.x = fmaf(w0, v0.x, acc.x); acc.y = fmaf(w0, v0.y, acc.y);
        acc.z = fmaf(w0, v0.z, acc.z); acc.w = fmaf(w0, v0.w, acc.w);
    }
    acc.x += __shfl_xor_sync(0xffffffffu, acc.x, 16);
    acc.y += __shfl_xor_sync(0xffffffffu, acc.y, 16);
    acc.z += __shfl_xor_sync(0xffffffffu, acc.z, 16);
    acc.w += __shfl_xor_sync(0xffffffffu, acc.w, 16);

    if (half == 0) {
        float4 r;
        if (CHEB) {
            float4 p = prev[(long)node * 16 + lh];
            r.x = 2.f * acc.x - p.x; r.y = 2.f * acc.y - p.y;
            r.z = 2.f * acc.z - p.z; r.w = 2.f * acc.w - p.w;
        } else {
            r = acc;
        }
        vout[(long)node * 16 + lh] = r;
    }
}

// ---------------- fused GEMM [N,256]@[256,256] + GRU epilogue --------------
__global__ void __launch_bounds__(256, 1)
k_gemm(const float* __restrict__ x, const float* __restrict__ Wlin,
       const float* __restrict__ blin, float* __restrict__ outbuf) {
    __shared__ float As[128 * 32];   // [row][k]
    __shared__ float Bs[32 * 256];   // [k][col]

    const int tid = threadIdx.x;
    const int tx = tid & 15;
    const int ty = tid >> 4;
    const long rowBase = (long)blockIdx.x * 128;

    const float* bases[4];
    bases[0] = x    + rowBase * FI;
    bases[1] = g_T1 + rowBase * FI;
    bases[2] = g_T2 + rowBase * FI;
    bases[3] = g_T3 + rowBase * FI;

    unsigned long long acc[8][8];
#pragma unroll
    for (int r = 0; r < 8; r++)
#pragma unroll
        for (int c = 0; c < 8; c++) acc[r][c] = 0ull;

#pragma unroll 1
    for (int t = 0; t < 8; t++) {
        const float* Ab = bases[t >> 1] + (t & 1) * 32;
#pragma unroll
        for (int i = 0; i < 4; i++) {
            int idx = tid + i * 256;
            int r = idx >> 3, c4 = idx & 7;
            ((float4*)As)[r * 8 + c4] = *(const float4*)(Ab + (long)r * FI + c4 * 4);
        }
#pragma unroll
        for (int i = 0; i < 8; i++) {
            int idx = tid + i * 256;
            ((float4*)Bs)[idx] = ((const float4*)g_B)[t * 2048 + idx];
        }
        __syncthreads();

#pragma unroll 2
        for (int k = 0; k < 32; k++) {
            unsigned long long a2[8], b2[8];
#pragma unroll
            for (int r = 0; r < 8; r++) {
                float a = As[(ty * 8 + r) * 32 + k];
                a2[r] = pk2(a, a);
            }
            const float* brow = Bs + k * 256 + tx;
#pragma unroll
            for (int c = 0; c < 8; c++)
                b2[c] = pk2(brow[c * 16], brow[c * 16 + 128]);
#pragma unroll
            for (int r = 0; r < 8; r++)
#pragma unroll
                for (int c = 0; c < 8; c++)
                    fma2(acc[r][c], a2[r], b2[c]);
        }
        __syncthreads();
    }

    // epilogue: H = (1-sigmoid(u))*tanh(v); h=relu(H);
    // logits = sqrt(rowsum(h)); out = h.Wlin + blin
    float wl[8], bu[8], bv[8];
#pragma unroll
    for (int c = 0; c < 8; c++) {
        int j = tx + 16 * c;
        wl[c] = __ldg(Wlin + j);
        bu[c] = g_bias[j];
        bv[c] = g_bias[j + 128];
    }
    const float bl = __ldg(blin);

#pragma unroll
    for (int r = 0; r < 8; r++) {
        float rs = 0.f, dt = 0.f;
#pragma unroll
        for (int c = 0; c < 8; c++) {
            float u, v;
            upk2(acc[r][c], u, v);
            u += bu[c];
            v += bv[c];
            float z  = __fdividef(1.f, 1.f + __expf(-u));            // sigmoid
            float th = 1.f - __fdividef(2.f, __expf(2.f * v) + 1.f); // tanh, inf-safe
            float h  = fmaxf((1.f - z) * th, 0.f);
            rs += h;
            dt = fmaf(h, wl[c], dt);
        }
        rs += __shfl_xor_sync(0xffffffffu, rs, 8);
        dt += __shfl_xor_sync(0xffffffffu, dt, 8);
        rs += __shfl_xor_sync(0xffffffffu, rs, 4);
        dt += __shfl_xor_sync(0xffffffffu, dt, 4);
        rs += __shfl_xor_sync(0xffffffffu, rs, 2);
        dt += __shfl_xor_sync(0xffffffffu, dt, 2);
        rs += __shfl_xor_sync(0xffffffffu, rs, 1);
        dt += __shfl_xor_sync(0xffffffffu, dt, 1);
        if (tx == 0) {
            long row = rowBase + ty * 8 + r;
            outbuf[row]      = dt + bl;      // out = h @ W_lin + b_lin
            outbuf[NN + row] = sqrtf(rs);    // logits = sqrt(rowsum(relu(H)))
        }
    }
}

// ---------------- launch orchestration -------------------------------------
extern "C" void kernel_launch(void* const* d_in, const int* in_sizes, int n_in,
                              void* d_out, int out_size) {
    const float* x  = (const float*)d_in[0];
    const void*  ei = d_in[1];                 // int32 or int64 — detected on device
    const float* ew = (const float*)d_in[2];
    const float* Wx = (const float*)d_in[3];
    // d_in[4] = W_h : provably unused (H==0 => cheb(H,*) == bias)
    const float* bx = (const float*)d_in[5];
    const float* bh = (const float*)d_in[6];
    const float* Wl = (const float*)d_in[7];
    const float* bl = (const float*)d_in[8];
    float* out = (float*)d_out;
    (void)in_sizes; (void)n_in; (void)out_size;

    void *pT1, *pT2, *pT3;
    cudaGetSymbolAddress(&pT1, g_T1);
    cudaGetSymbolAddress(&pT2, g_T2);
    cudaGetSymbolAddress(&pT3, g_T3);

    // ---- prep: detect dtype -> degree/hist -> dinv -> scan -> scatter -> pack
    k_zero   <<<NN / 256, 256>>>();
    k_detect <<<16, 256>>>((const int*)ei);
    k_setflag<<<1, 1>>>();
    k_deg    <<<NE / 256, 256>>>(ei, ew);
    k_dinv   <<<NN / 256, 256>>>();
    k_scan   <<<1, 1024>>>();
    k_scatter<<<NE / 256, 256>>>(ei, ew);
    k_pack   <<<256, 256>>>(Wx, bx, bh);

    // ---- Chebyshev: T1 = L x ; T2 = 2 L T1 - x ; T3 = 2 L T2 - T1
    k_spmm<false><<<NN / 8, 256>>>((const float4*)x, nullptr, (float4*)pT1);
    k_spmm<true> <<<NN / 8, 256>>>((const float4*)pT1, (const float4*)x,  (float4*)pT2);
    k_spmm<true> <<<NN / 8, 256>>>((const float4*)pT2, (const float4*)pT1, (float4*)pT3);

    // ---- fused GEMM + GRU + head
    k_gemm<<<NN / 128, 256>>>(x, Wl, bl, out);
}

// round 5
// speedup vs baseline: 1.3402x; 1.3402x over previous
#include <cuda_runtime.h>
#include <cuda_bf16.h>
#include <cstdint>

#define NN 131072
#define NE 4194304
#define FI 64

// ---------------- scratch (device globals: no allocation allowed) ----------
__device__ float g_deg [NN];         // degree, then dinv in-place
__device__ int   g_cnt [NN];         // in-degree histogram (by dst)
__device__ int   g_off [NN + 1];     // CSR row offsets (by dst)
__device__ int   g_cur [NN];         // scatter cursors
__device__ int   g_csrc[NE];         // CSR: src node per edge slot
__device__ float g_cw  [NE];         // CSR: normalized weight per edge slot
__device__ float g_T1[NN * FI];      // Tx1 = spmm(x)
__device__ float g_T2[NN * FI];      // Tx2 = 2*spmm(Tx1) - x
__device__ float g_T3[NN * FI];      // Tx3 = 2*spmm(Tx2) - Tx1
// B operand [chunk kb][n 0..255][k 0..63] bf16, SW128-pre-swizzled (32KB/chunk)
__device__ __nv_bfloat16 g_Bhi[4 * 256 * 64];
__device__ __nv_bfloat16 g_Blo[4 * 256 * 64];
__device__ float g_bias[256];        // b_x[g]+b_h[g] for gate0|gate2
__device__ int   g_any;              // detector: any odd word nonzero?
__device__ int   g_is64;             // 1 if edge_index is int64

// ---------------- edge-index access (dtype-robust, trap-proof) -------------
__device__ __forceinline__ int eidx(const void* ei, unsigned i) {
    int v;
    if (g_is64) v = (int)((const long long*)ei)[i];
    else        v = ((const int*)ei)[i];
    return v & (NN - 1);             // NN = 2^17: no-op for valid ids, trap-proof
}

// ---------------- helpers ----------------------------------------------------
__device__ __forceinline__ uint32_t smem_u32(const void* p) {
    uint32_t a;
    asm("{ .reg .u64 t; cvta.to.shared.u64 t, %1; cvt.u32.u64 %0, t; }"
        : "=r"(a) : "l"(p));
    return a;
}
#define SWZ128(o) ((o) ^ (((o) >> 3) & 0x70))

__device__ __forceinline__ void ldsm4(uint32_t& r0, uint32_t& r1, uint32_t& r2,
                                      uint32_t& r3, uint32_t addr) {
    asm volatile("ldmatrix.sync.aligned.m8n8.x4.shared.b16 {%0,%1,%2,%3}, [%4];"
                 : "=r"(r0), "=r"(r1), "=r"(r2), "=r"(r3) : "r"(addr));
}
__device__ __forceinline__ void mma16816(float* c, const uint32_t* a,
                                         uint32_t b0, uint32_t b1) {
    asm volatile("mma.sync.aligned.m16n8k16.row.col.f32.bf16.bf16.f32 "
                 "{%0,%1,%2,%3}, {%4,%5,%6,%7}, {%8,%9}, {%0,%1,%2,%3};"
                 : "+f"(c[0]), "+f"(c[1]), "+f"(c[2]), "+f"(c[3])
                 : "r"(a[0]), "r"(a[1]), "r"(a[2]), "r"(a[3]), "r"(b0), "r"(b1));
}
__device__ __forceinline__ float gru_h(float u, float v) {
    float z  = __fdividef(1.f, 1.f + __expf(-u));             // sigmoid
    float th = 1.f - __fdividef(2.f, __expf(2.f * v) + 1.f);  // tanh, inf-safe
    return fmaxf((1.f - z) * th, 0.f);                        // relu((1-z)*tanh)
}

// ---------------- prep kernels ---------------------------------------------
__global__ void k_zero() {
    int i = blockIdx.x * 256 + threadIdx.x;
    if (i < NN) { g_deg[i] = 0.f; g_cnt[i] = 0; }
    if (i == 0) { g_any = 0; }
}

// sample odd 32-bit words of the first 2*NE words: all-zero <=> int64 layout
__global__ void k_detect(const int* __restrict__ w) {
    int t = blockIdx.x * 256 + threadIdx.x;      // 4096 samples
    int stride = (2 * (NE / 4096));
    int v = w[(unsigned)(t * stride + 1)];
    if (__syncthreads_or(v != 0) && threadIdx.x == 0) atomicOr(&g_any, 1);
}
__global__ void k_setflag() { g_is64 = (g_any == 0); }

__global__ void k_deg(const void* __restrict__ ei, const float* __restrict__ ew) {
    unsigned e = blockIdx.x * 256 + threadIdx.x;
    if (e >= NE) return;
    atomicAdd(&g_deg[eidx(ei, e)], ew[e]);
    atomicAdd(&g_cnt[eidx(ei, NE + e)], 1);
}

__global__ void k_dinv() {
    int i = blockIdx.x * 256 + threadIdx.x;
    if (i < NN) {
        float d = g_deg[i];
        g_deg[i] = (d > 0.f) ? rsqrtf(d) : 0.f;
    }
}

// single-block exclusive scan of g_cnt -> g_off, g_cur  (1024 threads)
__global__ void k_scan() {
    __shared__ int wsum[32];
    __shared__ int carry_s;
    const int tid  = threadIdx.x;
    const int lane = tid & 31;
    const int w    = tid >> 5;
    int carry = 0;
    for (int base = 0; base < NN; base += 1024) {
        int v = g_cnt[base + tid];
        int x = v;
#pragma unroll
        for (int d = 1; d < 32; d <<= 1) {
            int y = __shfl_up_sync(0xffffffffu, x, d);
            if (lane >= d) x += y;
        }
        if (lane == 31) wsum[w] = x;
        __syncthreads();
        if (w == 0) {
            int s = wsum[lane];
#pragma unroll
            for (int d = 1; d < 32; d <<= 1) {
                int y = __shfl_up_sync(0xffffffffu, s, d);
                if (lane >= d) s += y;
            }
            wsum[lane] = s;
        }
        __syncthreads();
        int incl = x + (w > 0 ? wsum[w - 1] : 0) + carry;
        int excl = incl - v;
        g_off[base + tid] = excl;
        g_cur[base + tid] = excl;
        if (tid == 1023) carry_s = incl;
        __syncthreads();
        carry = carry_s;
        __syncthreads();
    }
    if (tid == 0) g_off[NN] = carry;
}

__global__ void k_scatter(const void* __restrict__ ei, const float* __restrict__ ew) {
    unsigned e = blockIdx.x * 256 + threadIdx.x;
    if (e >= NE) return;
    int s = eidx(ei, e);
    int d = eidx(ei, NE + e);
    float w = -g_deg[s] * ew[e] * g_deg[d];
    int pos = atomicAdd(&g_cur[d], 1);
    if (pos < NE) { g_csrc[pos] = s; g_cw[pos] = w; }
}

// Pack B for MMA: B_mma[n][k] = W[k][n]; split hi/lo bf16; SW128-pre-swizzled.
__global__ void k_pack(const float* __restrict__ Wx, const float* __restrict__ bx,
                       const float* __restrict__ bh) {
    int i = blockIdx.x * 256 + threadIdx.x;   // 65536 total
    int kb = i >> 14, n = (i >> 6) & 255, kk = i & 63;
    int g  = (n < 128) ? 0 : 2;
    int jj = n & 127;
    float w = Wx[(((size_t)(g * 4 + kb) * 64 + kk) * 128) + jj];
    __nv_bfloat16 hi = __float2bfloat16(w);
    __nv_bfloat16 lo = __float2bfloat16(w - __bfloat162float(hi));
    uint32_t off = SWZ128((uint32_t)(n * 128 + kk * 2));   // byte off in 32KB tile
    uint32_t idx = (uint32_t)kb * 16384 + (off >> 1);
    g_Bhi[idx] = hi;
    g_Blo[idx] = lo;
    if (kb == 0 && kk == 0) g_bias[n] = bx[g * 128 + jj] + bh[g * 128 + jj];
}

// ---------------- SpMM gather: out[d] = CHEB ? (2*sum - prev[d]) : sum ------
template <bool CHEB>
__global__ void __launch_bounds__(256)
k_spmm(const float4* __restrict__ vin, const float4* __restrict__ prev,
       float4* __restrict__ vout) {
    const int node = blockIdx.x * 8 + (threadIdx.x >> 5);
    const int lane = threadIdx.x & 31;
    const int lh   = lane & 15;
    const int half = lane >> 4;
    const int beg = g_off[node];
    const int end = g_off[node + 1];

    float4 acc = make_float4(0.f, 0.f, 0.f, 0.f);
    int i = beg + half;
    for (; i + 2 < end; i += 4) {
        int   s0 = g_csrc[i];
        int   s1 = g_csrc[i + 2];
        float w0 = g_cw[i];
        float w1 = g_cw[i + 2];
        float4 v0 = vin[(long)s0 * 16 + lh];
        float4 v1 = vin[(long)s1 * 16 + lh];
        acc.x = fmaf(w0, v0.x, acc.x); acc.y = fmaf(w0, v0.y, acc.y);
        acc.z = fmaf(w0, v0.z, acc.z); acc.w = fmaf(w0, v0.w, acc.w);
        acc.x = fmaf(w1, v1.x, acc.x); acc.y = fmaf(w1, v1.y, acc.y);
        acc.z = fmaf(w1, v1.z, acc.z); acc.w = fmaf(w1, v1.w, acc.w);
    }
    if (i < end) {
        int   s0 = g_csrc[i];
        float w0 = g_cw[i];
        float4 v0 = vin[(long)s0 * 16 + lh];
        acc.x = fmaf(w0, v0.x, acc.x); acc.y = fmaf(w0, v0.y, acc.y);
        acc.z = fmaf(w0, v0.z, acc.z); acc.w = fmaf(w0, v0.w, acc.w);
    }
    acc.x += __shfl_xor_sync(0xffffffffu, acc.x, 16);
    acc.y += __shfl_xor_sync(0xffffffffu, acc.y, 16);
    acc.z += __shfl_xor_sync(0xffffffffu, acc.z, 16);
    acc.w += __shfl_xor_sync(0xffffffffu, acc.w, 16);

    if (half == 0) {
        float4 r;
        if (CHEB) {
            float4 p = prev[(long)node * 16 + lh];
            r.x = 2.f * acc.x - p.x; r.y = 2.f * acc.y - p.y;
            r.z = 2.f * acc.z - p.z; r.w = 2.f * acc.w - p.w;
        } else {
            r = acc;
        }
        vout[(long)node * 16 + lh] = r;
    }
}

// ---------------- mma.sync GEMM [128 rows/CTA, N=256, K=256] + GRU epilogue -
// D = Ah*Bh + Al*Bh + Ah*Bl (bf16x3 split), fp32 accum in registers.
// SMEM (dynamic): [0..1024) row-reduce buffers; Ahi@1024 (16KB); Alo@17408;
//                 Bhi@33792 (32KB); Blo@66560 (32KB). Total 99328 B.
#define SM_AHI 1024
#define SM_ALO 17408
#define SM_BHI 33792
#define SM_BLO 66560
#define SM_DYN 99328

__global__ void __launch_bounds__(256, 1)
k_gemm_mma(const float* __restrict__ x, const float* __restrict__ Wlin,
           const float* __restrict__ blin, float* __restrict__ outbuf) {
    extern __shared__ char smem[];
    float* smf = (float*)smem;               // [0..128) rs, [128..256) dt
    const uint32_t sb  = smem_u32(smem);
    const int tid  = threadIdx.x;
    const int wid  = tid >> 5;
    const int lane = tid & 31;
    const int wm   = wid & 3;                // m quarter: rows wm*32..+31
    const int wn   = wid >> 2;               // n half pattern
    const long rowBase = (long)blockIdx.x * 128;

    if (tid < 128) { smf[tid] = 0.f; smf[128 + tid] = 0.f; }

    const float* bases[4] = { x    + rowBase * FI, g_T1 + rowBase * FI,
                              g_T2 + rowBase * FI, g_T3 + rowBase * FI };

    // acc[mt][tix][4]: mt = m-subtile (16 rows), tix 0-7 = u tiles (cols wn*64+i*8),
    // tix 8-15 = v tiles (cols +128). 128 fp32 regs.
    float acc[2][16][4];
#pragma unroll
    for (int mt = 0; mt < 2; mt++)
#pragma unroll
        for (int t = 0; t < 16; t++)
#pragma unroll
            for (int q = 0; q < 4; q++) acc[mt][t][q] = 0.f;

#pragma unroll 1
    for (int c = 0; c < 4; c++) {
        // --- stage A chunk: 128x64 fp32 -> hi/lo bf16, SW128 swizzled
        const float4* Asrc = (const float4*)bases[c];
#pragma unroll
        for (int it = 0; it < 8; it++) {
            int idx = tid + it * 256;           // 2048 float4
            int r  = idx >> 4;
            int c4 = idx & 15;
            float4 v = Asrc[r * 16 + c4];
            __nv_bfloat16 h0 = __float2bfloat16(v.x);
            __nv_bfloat16 h1 = __float2bfloat16(v.y);
            __nv_bfloat16 h2 = __float2bfloat16(v.z);
            __nv_bfloat16 h3 = __float2bfloat16(v.w);
            __nv_bfloat16 l0 = __float2bfloat16(v.x - __bfloat162float(h0));
            __nv_bfloat16 l1 = __float2bfloat16(v.y - __bfloat162float(h1));
            __nv_bfloat16 l2 = __float2bfloat16(v.z - __bfloat162float(h2));
            __nv_bfloat16 l3 = __float2bfloat16(v.w - __bfloat162float(h3));
            uint32_t off = SWZ128((uint32_t)(r * 128 + c4 * 8));
            *(__nv_bfloat162*)(smem + SM_AHI + off)     = __nv_bfloat162(h0, h1);
            *(__nv_bfloat162*)(smem + SM_AHI + off + 4) = __nv_bfloat162(h2, h3);
            *(__nv_bfloat162*)(smem + SM_ALO + off)     = __nv_bfloat162(l0, l1);
            *(__nv_bfloat162*)(smem + SM_ALO + off + 4) = __nv_bfloat162(l2, l3);
        }
        // --- stage B chunk: straight uint4 copy (pre-swizzled in global)
        const uint4* bh_src = (const uint4*)(g_Bhi + (size_t)c * 16384);
        const uint4* bl_src = (const uint4*)(g_Blo + (size_t)c * 16384);
#pragma unroll
        for (int it = 0; it < 8; it++) {
            int idx = tid + it * 256;           // 2048 uint4
            ((uint4*)(smem + SM_BHI))[idx] = bh_src[idx];
            ((uint4*)(smem + SM_BLO))[idx] = bl_src[idx];
        }
        __syncthreads();

        // --- MMA core: 3 split-combos × 4 k16-steps × (2 m-tiles × 16 n-tiles)
#pragma unroll 1
        for (int sp = 0; sp < 3; sp++) {
            const uint32_t Aoff = (sp == 1) ? SM_ALO : SM_AHI;
            const uint32_t Boff = (sp == 2) ? SM_BLO : SM_BHI;
#pragma unroll
            for (int ks = 0; ks < 4; ks++) {
                // A fragments for both 16-row subtiles
                uint32_t a[2][4];
#pragma unroll
                for (int mt = 0; mt < 2; mt++) {
                    int r = wm * 32 + mt * 16 + (lane & 15);
                    int g = 2 * ks + (lane >> 4);
                    uint32_t ad = sb + Aoff + (uint32_t)(r * 128 + ((g ^ (r & 7)) << 4));
                    ldsm4(a[mt][0], a[mt][1], a[mt][2], a[mt][3], ad);
                }
                // B fragments: 8 x4-loads = 16 n-tiles
#pragma unroll
                for (int p = 0; p < 8; p++) {
                    int tix = (p < 4) ? (2 * p) : (8 + 2 * (p - 4));
                    int ntb = wn * 8 + ((p < 4) ? (2 * p) : (16 + 2 * (p - 4)));
                    int n = ntb * 8 + (lane & 7) + ((lane >> 4) << 3);
                    int g = 2 * ks + ((lane >> 3) & 1);
                    uint32_t bd = sb + Boff + (uint32_t)(n * 128 + ((g ^ (n & 7)) << 4));
                    uint32_t b0, b1, b2, b3;
                    ldsm4(b0, b1, b2, b3, bd);
                    mma16816(acc[0][tix],     a[0], b0, b1);
                    mma16816(acc[1][tix],     a[1], b0, b1);
                    mma16816(acc[0][tix + 1], a[0], b2, b3);
                    mma16816(acc[1][tix + 1], a[1], b2, b3);
                }
            }
        }
        __syncthreads();
    }

    // ---- GRU epilogue on register accumulators -----------------------------
    const float bl = __ldg(blin);
#pragma unroll
    for (int mt = 0; mt < 2; mt++) {
        float rs0 = 0.f, dt0 = 0.f, rs1 = 0.f, dt1 = 0.f;
#pragma unroll
        for (int i = 0; i < 8; i++) {
            int j0 = wn * 64 + i * 8 + 2 * (lane & 3);
            float bu0 = __ldg(g_bias + j0),       bu1 = __ldg(g_bias + j0 + 1);
            float bv0 = __ldg(g_bias + j0 + 128), bv1 = __ldg(g_bias + j0 + 129);
            float w0  = __ldg(Wlin + j0),         w1  = __ldg(Wlin + j0 + 1);
            float h00 = gru_h(acc[mt][i][0] + bu0, acc[mt][8 + i][0] + bv0);
            float h01 = gru_h(acc[mt][i][1] + bu1, acc[mt][8 + i][1] + bv1);
            float h10 = gru_h(acc[mt][i][2] + bu0, acc[mt][8 + i][2] + bv0);
            float h11 = gru_h(acc[mt][i][3] + bu1, acc[mt][8 + i][3] + bv1);
            rs0 += h00 + h01; dt0 = fmaf(h00, w0, fmaf(h01, w1, dt0));
            rs1 += h10 + h11; dt1 = fmaf(h10, w0, fmaf(h11, w1, dt1));
        }
        // reduce over the 4 lanes sharing a row (bits 0-1 of lane)
#pragma unroll
        for (int s = 1; s < 4; s <<= 1) {
            rs0 += __shfl_xor_sync(0xffffffffu, rs0, s);
            dt0 += __shfl_xor_sync(0xffffffffu, dt0, s);
            rs1 += __shfl_xor_sync(0xffffffffu, rs1, s);
            dt1 += __shfl_xor_sync(0xffffffffu, dt1, s);
        }
        if ((lane & 3) == 0) {
            int r = wm * 32 + mt * 16 + (lane >> 2);
            atomicAdd(&smf[r],           rs0);
            atomicAdd(&smf[128 + r],     dt0);
            atomicAdd(&smf[r + 8],       rs1);
            atomicAdd(&smf[128 + r + 8], dt1);
        }
    }
    __syncthreads();
    if (tid < 128) {
        long grow = rowBase + tid;
        outbuf[grow]      = smf[128 + tid] + bl;   // out = h @ W_lin + b_lin
        outbuf[NN + grow] = sqrtf(smf[tid]);       // logits = sqrt(rowsum(relu(H)))
    }
}

// ---------------- launch orchestration -------------------------------------
extern "C" void kernel_launch(void* const* d_in, const int* in_sizes, int n_in,
                              void* d_out, int out_size) {
    const float* x  = (const float*)d_in[0];
    const void*  ei = d_in[1];                 // int32 or int64 — detected on device
    const float* ew = (const float*)d_in[2];
    const float* Wx = (const float*)d_in[3];
    // d_in[4] = W_h : provably unused (H==0 => cheb(H,*) == bias)
    const float* bx = (const float*)d_in[5];
    const float* bh = (const float*)d_in[6];
    const float* Wl = (const float*)d_in[7];
    const float* bl = (const float*)d_in[8];
    float* out = (float*)d_out;
    (void)in_sizes; (void)n_in; (void)out_size;

    void *pT1, *pT2, *pT3;
    cudaGetSymbolAddress(&pT1, g_T1);
    cudaGetSymbolAddress(&pT2, g_T2);
    cudaGetSymbolAddress(&pT3, g_T3);

    cudaFuncSetAttribute(k_gemm_mma, cudaFuncAttributeMaxDynamicSharedMemorySize, SM_DYN);

    // ---- prep: detect dtype -> degree/hist -> dinv -> scan -> scatter -> pack
    k_zero   <<<NN / 256, 256>>>();
    k_detect <<<16, 256>>>((const int*)ei);
    k_setflag<<<1, 1>>>();
    k_deg    <<<NE / 256, 256>>>(ei, ew);
    k_dinv   <<<NN / 256, 256>>>();
    k_scan   <<<1, 1024>>>();
    k_scatter<<<NE / 256, 256>>>(ei, ew);
    k_pack   <<<256, 256>>>(Wx, bx, bh);

    // ---- Chebyshev: T1 = L x ; T2 = 2 L T1 - x ; T3 = 2 L T2 - T1
    k_spmm<false><<<NN / 8, 256>>>((const float4*)x, nullptr, (float4*)pT1);
    k_spmm<true> <<<NN / 8, 256>>>((const float4*)pT1, (const float4*)x,  (float4*)pT2);
    k_spmm<true> <<<NN / 8, 256>>>((const float4*)pT2, (const float4*)pT1, (float4*)pT3);

    // ---- fused mma.sync GEMM + GRU + head
    k_gemm_mma<<<NN / 128, 256, SM_DYN>>>(x, Wl, bl, out);
}